// round 10
// baseline (speedup 1.0000x reference)
#include <cuda_runtime.h>
#include <cstdint>

#define B_ 128
#define T_ 256
#define H_ 512
#define G_ 2048   // 4*H
#define PAD_ 36

// ---- static scratch ----
__device__ float g_xproj[(size_t)2 * T_ * B_ * G_];   // [dir][t][b][4H]
__device__ float g_hseq [(size_t)2 * T_ * B_ * H_];   // [dir][t][b][H] (tf32-rounded)
__device__ float g_hT[2][2][H_][B_];                  // [parity][dir][hcol][b]
__device__ float g_xR[(size_t)B_ * T_ * H_];          // tf32-rounded x
__device__ float g_Wfrag[(size_t)4 * G_ * H_];        // fragment-swizzled tf32 Wx
__device__ unsigned g_garr[8 * 32];                   // per-group arrive counters
__device__ unsigned g_gdone[8 * 32];

// ---------------- helpers ----------------
__device__ __forceinline__ float2 ffma2(float2 a, float2 b, float2 c) {
    unsigned long long aa = *(unsigned long long*)&a;
    unsigned long long bb = *(unsigned long long*)&b;
    unsigned long long cc = *(unsigned long long*)&c;
    unsigned long long dd;
    asm("fma.rn.f32x2 %0, %1, %2, %3;" : "=l"(dd) : "l"(aa), "l"(bb), "l"(cc));
    return *(float2*)&dd;
}
__device__ __forceinline__ float sig_(float x) { return 1.0f / (1.0f + __expf(-x)); }
__device__ __forceinline__ float rtf32(float v) {
    uint32_t u; asm("cvt.rna.tf32.f32 %0, %1;" : "=r"(u) : "f"(v));
    return __uint_as_float(u);
}
__device__ __forceinline__ void cp16(void* smem, const void* gmem) {
    unsigned s = (unsigned)__cvta_generic_to_shared(smem);
    asm volatile("cp.async.cg.shared.global [%0], [%1], 16;" :: "r"(s), "l"(gmem));
}
#define CP_COMMIT()  asm volatile("cp.async.commit_group;")
#define CP_WAIT1()   asm volatile("cp.async.wait_group 1;")
#define CP_WAIT2()   asm volatile("cp.async.wait_group 2;")
#define CP_WAITALL() asm volatile("cp.async.wait_group 0;")

__device__ __forceinline__ void mma8(float* c, const uint32_t* a, const uint32_t* b) {
    asm volatile(
        "mma.sync.aligned.m16n8k8.row.col.f32.tf32.tf32.f32 "
        "{%0,%1,%2,%3}, {%4,%5,%6,%7}, {%8,%9}, {%0,%1,%2,%3};"
        : "+f"(c[0]), "+f"(c[1]), "+f"(c[2]), "+f"(c[3])
        : "r"(a[0]), "r"(a[1]), "r"(a[2]), "r"(a[3]), "r"(b[0]), "r"(b[1]));
}

// group-local barrier: 16 CTAs per (row-tile, dir) group; nanosleep backoff spin
__device__ __forceinline__ void groupbar(int gid, unsigned phase) {
    __syncthreads();
    if (threadIdx.x == 0) {
        __threadfence();
        atomicAdd(&g_garr[gid * 32], 1u);
        const unsigned target = phase * 16u;
        unsigned r;
        do {
            asm volatile("ld.global.acquire.gpu.u32 %0, [%1];"
                         : "=r"(r) : "l"(&g_garr[gid * 32]));
            if (r >= target) break;
            __nanosleep(32);
        } while (true);
    }
    __syncthreads();
}

// ---------------------------------------------------------------------------
// Prep 1: tf32-round x into g_xR
// ---------------------------------------------------------------------------
__global__ __launch_bounds__(256, 4)
void round_x(const float* __restrict__ x)
{
    const size_t i = ((size_t)blockIdx.x * 256 + threadIdx.x) * 4;
    const float4 v = *(const float4*)(x + i);
    float4 o;
    o.x = rtf32(v.x); o.y = rtf32(v.y); o.z = rtf32(v.z); o.w = rtf32(v.w);
    *(float4*)(g_xR + i) = o;
}

// ---------------------------------------------------------------------------
// Prep 2: fragment-swizzled tf32 Wx
// ---------------------------------------------------------------------------
__global__ __launch_bounds__(256, 4)
void prep_wfrag(const float* __restrict__ Wx)
{
    const uint32_t cid = blockIdx.x * 256 + threadIdx.x;   // 524288 total
    const int r  = cid & 3;
    const int kb = (cid >> 2) & 15;
    const int n  = (cid >> 6) & 2047;
    const int p  = cid >> 17;
    const float* W = Wx + (size_t)p * H_ * G_;
    float* o = g_Wfrag + (size_t)cid * 8;
    #pragma unroll
    for (int ks = 0; ks < 4; ks++)
        #pragma unroll
        for (int b01 = 0; b01 < 2; b01++) {
            const int k = kb * 32 + ks * 8 + r + 4 * b01;
            o[ks * 2 + b01] = rtf32(W[(size_t)k * G_ + n]);
        }
}

// ---------------------------------------------------------------------------
// tf32 mma.sync xproj: D[128 x 128]/CTA, K=512 in 16 k-blocks.
// ONLY change vs R9: 512 threads / 16 warps (4m x 4n, 32x32 warp tile,
// 4 warps per SMSP) instead of 256/8. B fragments single-buffered (the
// extra warps hide the L2 latency); same math order -> same numerics.
// ---------------------------------------------------------------------------
#define XP_SMEM (3 * 128 * PAD_ * 4)

__global__ __launch_bounds__(512, 1)
void xproj_mma(const float* __restrict__ bias, int layer)
{
    extern __shared__ float sA[];   // [3][128][PAD_]

    const int tid = threadIdx.x;
    const int lane = tid & 31, wid = tid >> 5;     // wid 0..15
    const int wm = wid & 3, wn = wid >> 2;         // 4m x 4n
    const int tg = lane >> 2, r4 = lane & 3;
    const int t = blockIdx.x, d = blockIdx.z;
    const int n0 = blockIdx.y * 128;
    const int l2d = layer * 2 + d;

    const float* Ab; size_t strA;
    if (layer == 0) {
        const int ts = d ? (T_ - 1 - t) : t;
        Ab = g_xR + (size_t)ts * H_;
        strA = (size_t)T_ * H_;
    } else {
        Ab = g_hseq + ((size_t)d * T_ + t) * B_ * H_;
        strA = H_;
    }

    const float* pB[4];
    #pragma unroll
    for (int nt = 0; nt < 4; nt++) {
        const int n = n0 + wn * 32 + nt * 8 + tg;
        pB[nt] = g_Wfrag + ((size_t)((l2d * 2048 + n) * 64 + r4)) * 8;
    }

    // A tile 128x32 floats = 1024 16B-chunks, 512 threads -> 2 chunks each
    const int crow[2] = {tid >> 3, (512 + tid) >> 3};
    const int cc4 = tid & 7;

    #define ISSUE(st, kb) do {                                               \
        _Pragma("unroll")                                                    \
        for (int i = 0; i < 2; i++)                                          \
            cp16(&sA[(st) * (128 * PAD_) + crow[i] * PAD_ + cc4 * 4],        \
                 Ab + (size_t)crow[i] * strA + (kb) * 32 + cc4 * 4);         \
        CP_COMMIT();                                                         \
    } while (0)

    float acc[2][4][4];
    #pragma unroll
    for (int mt = 0; mt < 2; mt++)
        #pragma unroll
        for (int nt = 0; nt < 4; nt++)
            #pragma unroll
            for (int i = 0; i < 4; i++) acc[mt][nt][i] = 0.f;

    ISSUE(0, 0);
    ISSUE(1, 1);

    for (int kb = 0; kb < 16; kb++) {
        float4 bt[4][2];
        #pragma unroll
        for (int nt = 0; nt < 4; nt++) {
            bt[nt][0] = *(const float4*)(pB[nt] + kb * 32);
            bt[nt][1] = *(const float4*)(pB[nt] + kb * 32 + 4);
        }

        if (kb == 15) { CP_WAITALL(); } else { CP_WAIT1(); }
        __syncthreads();
        if (kb + 2 < 16) ISSUE((kb + 2) % 3, kb + 2);

        const float* sAs = sA + (kb % 3) * (128 * PAD_);
        #pragma unroll
        for (int ks = 0; ks < 4; ks++) {
            uint32_t a[2][4];
            #pragma unroll
            for (int mt = 0; mt < 2; mt++) {
                const int m = wm * 32 + mt * 16 + tg;
                const int k = ks * 8 + r4;
                a[mt][0] = __float_as_uint(sAs[m * PAD_ + k]);
                a[mt][1] = __float_as_uint(sAs[(m + 8) * PAD_ + k]);
                a[mt][2] = __float_as_uint(sAs[m * PAD_ + k + 4]);
                a[mt][3] = __float_as_uint(sAs[(m + 8) * PAD_ + k + 4]);
            }
            #pragma unroll
            for (int mt = 0; mt < 2; mt++)
                #pragma unroll
                for (int nt = 0; nt < 4; nt++) {
                    const float* bf = (ks < 2) ? (const float*)&bt[nt][0]
                                               : (const float*)&bt[nt][1];
                    uint32_t b2[2];
                    b2[0] = __float_as_uint(bf[(ks & 1) * 2]);
                    b2[1] = __float_as_uint(bf[(ks & 1) * 2 + 1]);
                    mma8(acc[mt][nt], a[mt], b2);
                }
        }
    }
    #undef ISSUE

    float* ob = g_xproj + ((size_t)d * T_ + t) * B_ * G_;
    const float* bp = bias + (size_t)l2d * G_;
    #pragma unroll
    for (int nt = 0; nt < 4; nt++) {
        const int n = n0 + wn * 32 + nt * 8 + 2 * r4;
        const float2 bv = *(const float2*)(bp + n);
        #pragma unroll
        for (int mt = 0; mt < 2; mt++) {
            const int m = wm * 32 + mt * 16 + tg;
            float2 lo = make_float2(acc[mt][nt][0] + bv.x, acc[mt][nt][1] + bv.y);
            float2 hi = make_float2(acc[mt][nt][2] + bv.x, acc[mt][nt][3] + bv.y);
            *(float2*)(ob + (size_t)m * G_ + n)       = lo;
            *(float2*)(ob + (size_t)(m + 8) * G_ + n) = hi;
        }
    }
}

// ---------------------------------------------------------------------------
// Persistent recurrence — byte-identical to R8/R9 (proven config)
// ---------------------------------------------------------------------------
__global__ __launch_bounds__(128, 1)
void lstm_persist(const float* __restrict__ Wh, float* __restrict__ out, int layer)
{
    __shared__ float sW[4][16][128];
    __shared__ float sA[4][16][32];

    const int tid = threadIdx.x;
    const int tx = tid & 15;
    const int ty = tid >> 4;
    const int bidx = blockIdx.x;
    const int d   = bidx >> 6;
    const int rt  = (bidx >> 4) & 3;
    const int hcT = bidx & 15;
    const int gid = bidx >> 4;        // 0..7 = (d, rt) group
    const int b0  = rt * 32;
    const int hc0 = hcT * 32;
    const int hc  = hc0 + tx * 2;
    const int r0  = b0 + ty * 4;

    const float* Wb = Wh + (size_t)(layer * 2 + d) * H_ * G_;

    int wk[4], wc[4];
    const float* wsrc[4];
    #pragma unroll
    for (int j = 0; j < 4; j++) {
        const int idx = j * 128 + tid;
        const int k = idx >> 5, c16 = idx & 31;
        const int gate = c16 >> 3, part = c16 & 7;
        wk[j] = k; wc[j] = c16 * 4;
        wsrc[j] = Wb + (size_t)k * G_ + gate * H_ + hc0 + part * 4;
    }
    const int ak = tid >> 3, ac = (tid & 7) * 4;

    float2 cst[4];
    #pragma unroll
    for (int r = 0; r < 4; r++) cst[r] = make_float2(0.f, 0.f);

    for (int t = 0; t < T_; t++) {
        const int p = t & 1;
        const float* xb = g_xproj + ((size_t)d * T_ + t) * B_ * G_;
        float2 xp[4][4];
        #pragma unroll
        for (int r = 0; r < 4; r++)
            #pragma unroll
            for (int g = 0; g < 4; g++)
                xp[r][g] = *(const float2*)(xb + (size_t)(r0 + r) * G_ + g * H_ + hc);

        float2 acc[4][4];
        #pragma unroll
        for (int r = 0; r < 4; r++)
            #pragma unroll
            for (int g = 0; g < 4; g++) acc[r][g] = make_float2(0.f, 0.f);

        if (t > 0) {
            const float* hsrc = &g_hT[p ^ 1][d][0][0];
            #define ISSUE2(st, kb) do {                                          \
                _Pragma("unroll")                                                \
                for (int j = 0; j < 4; j++)                                      \
                    cp16(&sW[st][wk[j]][wc[j]], wsrc[j] + (size_t)(kb) * G_);    \
                cp16(&sA[st][ak][ac], hsrc + (size_t)((kb) + ak) * B_ + b0 + ac);\
                CP_COMMIT();                                                     \
            } while (0)

            ISSUE2(0, 0); ISSUE2(1, 16); ISSUE2(2, 32);

            for (int kbi = 0; kbi < 32; kbi++) {
                CP_WAIT2();
                __syncthreads();
                const int s = kbi & 3;
                #pragma unroll
                for (int k = 0; k < 16; k++) {
                    const float4 av = *(const float4*)&sA[s][k][ty * 4];
                    float2 bg[4];
                    #pragma unroll
                    for (int g = 0; g < 4; g++)
                        bg[g] = *(const float2*)&sW[s][k][g * 32 + tx * 2];
                    const float ar[4] = {av.x, av.y, av.z, av.w};
                    #pragma unroll
                    for (int r = 0; r < 4; r++) {
                        const float2 a2 = make_float2(ar[r], ar[r]);
                        #pragma unroll
                        for (int g = 0; g < 4; g++)
                            acc[r][g] = ffma2(a2, bg[g], acc[r][g]);
                    }
                }
                const int nb = kbi + 3;
                if (nb < 32) ISSUE2(nb & 3, nb * 16);
            }
            #undef ISSUE2
        }

        float2 hv[4];
        #pragma unroll
        for (int r = 0; r < 4; r++) {
            const float i0 = sig_(acc[r][0].x + xp[r][0].x);
            const float i1 = sig_(acc[r][0].y + xp[r][0].y);
            const float f0 = sig_(acc[r][1].x + xp[r][1].x);
            const float f1 = sig_(acc[r][1].y + xp[r][1].y);
            const float q0 = tanhf(acc[r][2].x + xp[r][2].x);
            const float q1 = tanhf(acc[r][2].y + xp[r][2].y);
            const float o0 = sig_(acc[r][3].x + xp[r][3].x);
            const float o1 = sig_(acc[r][3].y + xp[r][3].y);
            cst[r].x = f0 * cst[r].x + i0 * q0;
            cst[r].y = f1 * cst[r].y + i1 * q1;
            hv[r] = make_float2(o0 * tanhf(cst[r].x), o1 * tanhf(cst[r].y));
        }

        const float4 ha = make_float4(hv[0].x, hv[1].x, hv[2].x, hv[3].x);
        const float4 hb = make_float4(hv[0].y, hv[1].y, hv[2].y, hv[3].y);
        *(float4*)&g_hT[p][d][hc][r0]     = ha;
        *(float4*)&g_hT[p][d][hc + 1][r0] = hb;

        if (layer == 0) {
            float* hs = g_hseq + ((size_t)d * T_ + t) * B_ * H_;
            #pragma unroll
            for (int r = 0; r < 4; r++) {
                float2 hr = make_float2(rtf32(hv[r].x), rtf32(hv[r].y));
                *(float2*)(hs + (size_t)(r0 + r) * H_ + hc) = hr;
            }
        } else {
            const int tr = d ? (T_ - 1 - t) : t;
            #pragma unroll
            for (int r = 0; r < 4; r++)
                *(float2*)(out + ((size_t)(r0 + r) * T_ + tr) * (2 * H_) + d * H_ + hc) = hv[r];
        }

        if (t < T_ - 1) groupbar(gid, (unsigned)(t + 1));
    }

    // per-group reset for next launch / graph replay
    __syncthreads();
    if (tid == 0) {
        __threadfence();
        const unsigned v = atomicAdd(&g_gdone[gid * 32], 1u);
        if (v == 15u) {
            atomicExch(&g_garr[gid * 32], 0u);
            atomicExch(&g_gdone[gid * 32], 0u);
        }
    }
}

extern "C" void kernel_launch(void* const* d_in, const int* in_sizes, int n_in,
                              void* d_out, int out_size)
{
    const float* x  = (const float*)d_in[0];
    const float* Wx = (const float*)d_in[1];
    const float* Wh = (const float*)d_in[2];
    const float* b  = (const float*)d_in[3];
    float* out = (float*)d_out;

    static bool attr_done = false;
    if (!attr_done) {
        cudaFuncSetAttribute(xproj_mma, cudaFuncAttributeMaxDynamicSharedMemorySize, XP_SMEM);
        attr_done = true;
    }

    round_x<<<(B_ * T_ * H_ / 4 + 255) / 256, 256>>>(x);
    prep_wfrag<<<2048, 256>>>(Wx);
    for (int l = 0; l < 2; l++) {
        xproj_mma<<<dim3(T_, 16, 2), 512, XP_SMEM>>>(b, l);
        lstm_persist<<<128, 128>>>(Wh, out, l);
    }
}

// round 11
// speedup vs baseline: 1.6850x; 1.6850x over previous
#include <cuda_runtime.h>
#include <cstdint>

#define B_ 128
#define T_ 256
#define H_ 512
#define G_ 2048   // 4*H
#define PAD_ 36

// ---- static scratch ----
__device__ float g_xproj[(size_t)2 * T_ * B_ * G_];   // [dir][t][b][4H]
__device__ float g_hseq [(size_t)2 * T_ * B_ * H_];   // [dir][t][b][H] (tf32-rounded)
__device__ float g_hT[2][2][H_][B_];                  // [parity][dir][hcol][b]
__device__ float g_xR[(size_t)B_ * T_ * H_];          // tf32-rounded x
__device__ float g_Wfrag[(size_t)4 * G_ * H_];        // fragment-swizzled tf32 Wx
__device__ unsigned g_garr[8 * 32];                   // per-group arrive counters
__device__ unsigned g_gdone[8 * 32];

// ---------------- helpers ----------------
__device__ __forceinline__ float2 ffma2(float2 a, float2 b, float2 c) {
    unsigned long long aa = *(unsigned long long*)&a;
    unsigned long long bb = *(unsigned long long*)&b;
    unsigned long long cc = *(unsigned long long*)&c;
    unsigned long long dd;
    asm("fma.rn.f32x2 %0, %1, %2, %3;" : "=l"(dd) : "l"(aa), "l"(bb), "l"(cc));
    return *(float2*)&dd;
}
__device__ __forceinline__ float sig_(float x) { return 1.0f / (1.0f + __expf(-x)); }
__device__ __forceinline__ float rtf32(float v) {
    uint32_t u; asm("cvt.rna.tf32.f32 %0, %1;" : "=r"(u) : "f"(v));
    return __uint_as_float(u);
}
__device__ __forceinline__ void cp16(void* smem, const void* gmem) {
    unsigned s = (unsigned)__cvta_generic_to_shared(smem);
    asm volatile("cp.async.cg.shared.global [%0], [%1], 16;" :: "r"(s), "l"(gmem));
}
#define CP_COMMIT()  asm volatile("cp.async.commit_group;")
#define CP_WAIT1()   asm volatile("cp.async.wait_group 1;")
#define CP_WAIT2()   asm volatile("cp.async.wait_group 2;")
#define CP_WAITALL() asm volatile("cp.async.wait_group 0;")

__device__ __forceinline__ void mma8(float* c, const uint32_t* a, const uint32_t* b) {
    asm volatile(
        "mma.sync.aligned.m16n8k8.row.col.f32.tf32.tf32.f32 "
        "{%0,%1,%2,%3}, {%4,%5,%6,%7}, {%8,%9}, {%0,%1,%2,%3};"
        : "+f"(c[0]), "+f"(c[1]), "+f"(c[2]), "+f"(c[3])
        : "r"(a[0]), "r"(a[1]), "r"(a[2]), "r"(a[3]), "r"(b[0]), "r"(b[1]));
}

// group-local barrier: 16 CTAs per (row-tile, dir) group; nanosleep backoff spin
__device__ __forceinline__ void groupbar(int gid, unsigned phase) {
    __syncthreads();
    if (threadIdx.x == 0) {
        __threadfence();
        atomicAdd(&g_garr[gid * 32], 1u);
        const unsigned target = phase * 16u;
        unsigned r;
        do {
            asm volatile("ld.global.acquire.gpu.u32 %0, [%1];"
                         : "=r"(r) : "l"(&g_garr[gid * 32]));
            if (r >= target) break;
            __nanosleep(32);
        } while (true);
    }
    __syncthreads();
}

// ---------------------------------------------------------------------------
// Prep 1: tf32-round x into g_xR
// ---------------------------------------------------------------------------
__global__ __launch_bounds__(256, 4)
void round_x(const float* __restrict__ x)
{
    const size_t i = ((size_t)blockIdx.x * 256 + threadIdx.x) * 4;
    const float4 v = *(const float4*)(x + i);
    float4 o;
    o.x = rtf32(v.x); o.y = rtf32(v.y); o.z = rtf32(v.z); o.w = rtf32(v.w);
    *(float4*)(g_xR + i) = o;
}

// ---------------------------------------------------------------------------
// Prep 2: fragment-swizzled tf32 Wx
// ---------------------------------------------------------------------------
__global__ __launch_bounds__(256, 4)
void prep_wfrag(const float* __restrict__ Wx)
{
    const uint32_t cid = blockIdx.x * 256 + threadIdx.x;   // 524288 total
    const int r  = cid & 3;
    const int kb = (cid >> 2) & 15;
    const int n  = (cid >> 6) & 2047;
    const int p  = cid >> 17;
    const float* W = Wx + (size_t)p * H_ * G_;
    float* o = g_Wfrag + (size_t)cid * 8;
    #pragma unroll
    for (int ks = 0; ks < 4; ks++)
        #pragma unroll
        for (int b01 = 0; b01 < 2; b01++) {
            const int k = kb * 32 + ks * 8 + r + 4 * b01;
            o[ks * 2 + b01] = rtf32(W[(size_t)k * G_ + n]);
        }
}

// ---------------------------------------------------------------------------
// tf32 mma.sync xproj (R8 single-buffered-B body).
// ONLY change vs R8/R9: __launch_bounds__(256, 2) -> 2 CTAs per SM
// (4 warps/SMSP) to hide the per-k-block stalls. No B-traffic duplication:
// same warp layout, two independent CTAs interleave.
// ---------------------------------------------------------------------------
#define XP_SMEM (3 * 128 * PAD_ * 4)

__global__ __launch_bounds__(256, 2)
void xproj_mma(const float* __restrict__ bias, int layer)
{
    extern __shared__ float sA[];   // [3][128][PAD_]

    const int tid = threadIdx.x;
    const int lane = tid & 31, wid = tid >> 5;
    const int wm = wid & 1, wn = wid >> 1;
    const int tg = lane >> 2, r4 = lane & 3;
    const int t = blockIdx.x, d = blockIdx.z;
    const int n0 = blockIdx.y * 128;
    const int l2d = layer * 2 + d;

    const float* Ab; size_t strA;
    if (layer == 0) {
        const int ts = d ? (T_ - 1 - t) : t;
        Ab = g_xR + (size_t)ts * H_;
        strA = (size_t)T_ * H_;
    } else {
        Ab = g_hseq + ((size_t)d * T_ + t) * B_ * H_;
        strA = H_;
    }

    const float* pB[4];
    #pragma unroll
    for (int nt = 0; nt < 4; nt++) {
        const int n = n0 + wn * 32 + nt * 8 + tg;
        pB[nt] = g_Wfrag + ((size_t)((l2d * 2048 + n) * 64 + r4)) * 8;
    }

    const int crow[4] = {tid >> 3, (256 + tid) >> 3, (512 + tid) >> 3, (768 + tid) >> 3};
    const int cc4 = tid & 7;

    #define ISSUE(st, kb) do {                                               \
        _Pragma("unroll")                                                    \
        for (int i = 0; i < 4; i++)                                          \
            cp16(&sA[(st) * (128 * PAD_) + crow[i] * PAD_ + cc4 * 4],        \
                 Ab + (size_t)crow[i] * strA + (kb) * 32 + cc4 * 4);         \
        CP_COMMIT();                                                         \
    } while (0)

    float acc[4][4][4];
    #pragma unroll
    for (int mt = 0; mt < 4; mt++)
        #pragma unroll
        for (int nt = 0; nt < 4; nt++)
            #pragma unroll
            for (int i = 0; i < 4; i++) acc[mt][nt][i] = 0.f;

    ISSUE(0, 0);
    ISSUE(1, 1);

    for (int kb = 0; kb < 16; kb++) {
        float4 bt[4][2];
        #pragma unroll
        for (int nt = 0; nt < 4; nt++) {
            bt[nt][0] = *(const float4*)(pB[nt] + kb * 32);
            bt[nt][1] = *(const float4*)(pB[nt] + kb * 32 + 4);
        }

        if (kb == 15) { CP_WAITALL(); } else { CP_WAIT1(); }
        __syncthreads();
        if (kb + 2 < 16) ISSUE((kb + 2) % 3, kb + 2);

        const float* sAs = sA + (kb % 3) * (128 * PAD_);
        #pragma unroll
        for (int ks = 0; ks < 4; ks++) {
            uint32_t a[4][4];
            #pragma unroll
            for (int mt = 0; mt < 4; mt++) {
                const int m = wm * 64 + mt * 16 + tg;
                const int k = ks * 8 + r4;
                a[mt][0] = __float_as_uint(sAs[m * PAD_ + k]);
                a[mt][1] = __float_as_uint(sAs[(m + 8) * PAD_ + k]);
                a[mt][2] = __float_as_uint(sAs[m * PAD_ + k + 4]);
                a[mt][3] = __float_as_uint(sAs[(m + 8) * PAD_ + k + 4]);
            }
            #pragma unroll
            for (int mt = 0; mt < 4; mt++)
                #pragma unroll
                for (int nt = 0; nt < 4; nt++) {
                    const float* bf = (ks < 2) ? (const float*)&bt[nt][0]
                                               : (const float*)&bt[nt][1];
                    uint32_t b2[2];
                    b2[0] = __float_as_uint(bf[(ks & 1) * 2]);
                    b2[1] = __float_as_uint(bf[(ks & 1) * 2 + 1]);
                    mma8(acc[mt][nt], a[mt], b2);
                }
        }
    }
    #undef ISSUE

    float* ob = g_xproj + ((size_t)d * T_ + t) * B_ * G_;
    const float* bp = bias + (size_t)l2d * G_;
    #pragma unroll
    for (int nt = 0; nt < 4; nt++) {
        const int n = n0 + wn * 32 + nt * 8 + 2 * r4;
        const float2 bv = *(const float2*)(bp + n);
        #pragma unroll
        for (int mt = 0; mt < 4; mt++) {
            const int m = wm * 64 + mt * 16 + tg;
            float2 lo = make_float2(acc[mt][nt][0] + bv.x, acc[mt][nt][1] + bv.y);
            float2 hi = make_float2(acc[mt][nt][2] + bv.x, acc[mt][nt][3] + bv.y);
            *(float2*)(ob + (size_t)m * G_ + n)       = lo;
            *(float2*)(ob + (size_t)(m + 8) * G_ + n) = hi;
        }
    }
}

// ---------------------------------------------------------------------------
// Persistent recurrence — byte-identical to R8/R9 (proven config)
// ---------------------------------------------------------------------------
__global__ __launch_bounds__(128, 1)
void lstm_persist(const float* __restrict__ Wh, float* __restrict__ out, int layer)
{
    __shared__ float sW[4][16][128];
    __shared__ float sA[4][16][32];

    const int tid = threadIdx.x;
    const int tx = tid & 15;
    const int ty = tid >> 4;
    const int bidx = blockIdx.x;
    const int d   = bidx >> 6;
    const int rt  = (bidx >> 4) & 3;
    const int hcT = bidx & 15;
    const int gid = bidx >> 4;        // 0..7 = (d, rt) group
    const int b0  = rt * 32;
    const int hc0 = hcT * 32;
    const int hc  = hc0 + tx * 2;
    const int r0  = b0 + ty * 4;

    const float* Wb = Wh + (size_t)(layer * 2 + d) * H_ * G_;

    int wk[4], wc[4];
    const float* wsrc[4];
    #pragma unroll
    for (int j = 0; j < 4; j++) {
        const int idx = j * 128 + tid;
        const int k = idx >> 5, c16 = idx & 31;
        const int gate = c16 >> 3, part = c16 & 7;
        wk[j] = k; wc[j] = c16 * 4;
        wsrc[j] = Wb + (size_t)k * G_ + gate * H_ + hc0 + part * 4;
    }
    const int ak = tid >> 3, ac = (tid & 7) * 4;

    float2 cst[4];
    #pragma unroll
    for (int r = 0; r < 4; r++) cst[r] = make_float2(0.f, 0.f);

    for (int t = 0; t < T_; t++) {
        const int p = t & 1;
        const float* xb = g_xproj + ((size_t)d * T_ + t) * B_ * G_;
        float2 xp[4][4];
        #pragma unroll
        for (int r = 0; r < 4; r++)
            #pragma unroll
            for (int g = 0; g < 4; g++)
                xp[r][g] = *(const float2*)(xb + (size_t)(r0 + r) * G_ + g * H_ + hc);

        float2 acc[4][4];
        #pragma unroll
        for (int r = 0; r < 4; r++)
            #pragma unroll
            for (int g = 0; g < 4; g++) acc[r][g] = make_float2(0.f, 0.f);

        if (t > 0) {
            const float* hsrc = &g_hT[p ^ 1][d][0][0];
            #define ISSUE2(st, kb) do {                                          \
                _Pragma("unroll")                                                \
                for (int j = 0; j < 4; j++)                                      \
                    cp16(&sW[st][wk[j]][wc[j]], wsrc[j] + (size_t)(kb) * G_);    \
                cp16(&sA[st][ak][ac], hsrc + (size_t)((kb) + ak) * B_ + b0 + ac);\
                CP_COMMIT();                                                     \
            } while (0)

            ISSUE2(0, 0); ISSUE2(1, 16); ISSUE2(2, 32);

            for (int kbi = 0; kbi < 32; kbi++) {
                CP_WAIT2();
                __syncthreads();
                const int s = kbi & 3;
                #pragma unroll
                for (int k = 0; k < 16; k++) {
                    const float4 av = *(const float4*)&sA[s][k][ty * 4];
                    float2 bg[4];
                    #pragma unroll
                    for (int g = 0; g < 4; g++)
                        bg[g] = *(const float2*)&sW[s][k][g * 32 + tx * 2];
                    const float ar[4] = {av.x, av.y, av.z, av.w};
                    #pragma unroll
                    for (int r = 0; r < 4; r++) {
                        const float2 a2 = make_float2(ar[r], ar[r]);
                        #pragma unroll
                        for (int g = 0; g < 4; g++)
                            acc[r][g] = ffma2(a2, bg[g], acc[r][g]);
                    }
                }
                const int nb = kbi + 3;
                if (nb < 32) ISSUE2(nb & 3, nb * 16);
            }
            #undef ISSUE2
        }

        float2 hv[4];
        #pragma unroll
        for (int r = 0; r < 4; r++) {
            const float i0 = sig_(acc[r][0].x + xp[r][0].x);
            const float i1 = sig_(acc[r][0].y + xp[r][0].y);
            const float f0 = sig_(acc[r][1].x + xp[r][1].x);
            const float f1 = sig_(acc[r][1].y + xp[r][1].y);
            const float q0 = tanhf(acc[r][2].x + xp[r][2].x);
            const float q1 = tanhf(acc[r][2].y + xp[r][2].y);
            const float o0 = sig_(acc[r][3].x + xp[r][3].x);
            const float o1 = sig_(acc[r][3].y + xp[r][3].y);
            cst[r].x = f0 * cst[r].x + i0 * q0;
            cst[r].y = f1 * cst[r].y + i1 * q1;
            hv[r] = make_float2(o0 * tanhf(cst[r].x), o1 * tanhf(cst[r].y));
        }

        const float4 ha = make_float4(hv[0].x, hv[1].x, hv[2].x, hv[3].x);
        const float4 hb = make_float4(hv[0].y, hv[1].y, hv[2].y, hv[3].y);
        *(float4*)&g_hT[p][d][hc][r0]     = ha;
        *(float4*)&g_hT[p][d][hc + 1][r0] = hb;

        if (layer == 0) {
            float* hs = g_hseq + ((size_t)d * T_ + t) * B_ * H_;
            #pragma unroll
            for (int r = 0; r < 4; r++) {
                float2 hr = make_float2(rtf32(hv[r].x), rtf32(hv[r].y));
                *(float2*)(hs + (size_t)(r0 + r) * H_ + hc) = hr;
            }
        } else {
            const int tr = d ? (T_ - 1 - t) : t;
            #pragma unroll
            for (int r = 0; r < 4; r++)
                *(float2*)(out + ((size_t)(r0 + r) * T_ + tr) * (2 * H_) + d * H_ + hc) = hv[r];
        }

        if (t < T_ - 1) groupbar(gid, (unsigned)(t + 1));
    }

    // per-group reset for next launch / graph replay
    __syncthreads();
    if (tid == 0) {
        __threadfence();
        const unsigned v = atomicAdd(&g_gdone[gid * 32], 1u);
        if (v == 15u) {
            atomicExch(&g_garr[gid * 32], 0u);
            atomicExch(&g_gdone[gid * 32], 0u);
        }
    }
}

extern "C" void kernel_launch(void* const* d_in, const int* in_sizes, int n_in,
                              void* d_out, int out_size)
{
    const float* x  = (const float*)d_in[0];
    const float* Wx = (const float*)d_in[1];
    const float* Wh = (const float*)d_in[2];
    const float* b  = (const float*)d_in[3];
    float* out = (float*)d_out;

    static bool attr_done = false;
    if (!attr_done) {
        cudaFuncSetAttribute(xproj_mma, cudaFuncAttributeMaxDynamicSharedMemorySize, XP_SMEM);
        attr_done = true;
    }

    round_x<<<(B_ * T_ * H_ / 4 + 255) / 256, 256>>>(x);
    prep_wfrag<<<2048, 256>>>(Wx);
    for (int l = 0; l < 2; l++) {
        xproj_mma<<<dim3(T_, 16, 2), 256, XP_SMEM>>>(b, l);
        lstm_persist<<<128, 128>>>(Wh, out, l);
    }
}

// round 13
// speedup vs baseline: 1.8079x; 1.0730x over previous
#include <cuda_runtime.h>
#include <cuda_fp16.h>
#include <cstdint>

#define B_ 128
#define T_ 256
#define H_ 512
#define G_ 2048   // 4*H
#define PADH 40   // half-element row stride for A smem (conflict-free)

// ---- static scratch ----
__device__ float  g_xproj[(size_t)2 * T_ * B_ * G_];   // [dir][t][b][4H] f32
__device__ __half g_hseqh[(size_t)2 * T_ * B_ * H_];   // [dir][t][b][H] fp16
__device__ float  g_hT[2][2][H_][B_];                  // [parity][dir][hcol][b]
__device__ __half g_xh[(size_t)B_ * T_ * H_];          // fp16-rounded x
__device__ __half g_Wfragh[(size_t)4 * G_ * H_];       // fragment-packed fp16 Wx
__device__ unsigned g_garr[8 * 32];
__device__ unsigned g_gdone[8 * 32];

// ---------------- helpers ----------------
__device__ __forceinline__ float2 ffma2(float2 a, float2 b, float2 c) {
    unsigned long long aa = *(unsigned long long*)&a;
    unsigned long long bb = *(unsigned long long*)&b;
    unsigned long long cc = *(unsigned long long*)&c;
    unsigned long long dd;
    asm("fma.rn.f32x2 %0, %1, %2, %3;" : "=l"(dd) : "l"(aa), "l"(bb), "l"(cc));
    return *(float2*)&dd;
}
__device__ __forceinline__ float sig_(float x) { return 1.0f / (1.0f + __expf(-x)); }
__device__ __forceinline__ void cp16(void* smem, const void* gmem) {
    unsigned s = (unsigned)__cvta_generic_to_shared(smem);
    asm volatile("cp.async.cg.shared.global [%0], [%1], 16;" :: "r"(s), "l"(gmem));
}
#define CP_COMMIT()  asm volatile("cp.async.commit_group;")
#define CP_WAIT1()   asm volatile("cp.async.wait_group 1;")
#define CP_WAIT2()   asm volatile("cp.async.wait_group 2;")
#define CP_WAITALL() asm volatile("cp.async.wait_group 0;")

// fp16 m16n8k16 mma, f32 accumulate
__device__ __forceinline__ void mma16(float* c, const uint32_t* a, const uint32_t* b) {
    asm volatile(
        "mma.sync.aligned.m16n8k16.row.col.f32.f16.f16.f32 "
        "{%0,%1,%2,%3}, {%4,%5,%6,%7}, {%8,%9}, {%0,%1,%2,%3};"
        : "+f"(c[0]), "+f"(c[1]), "+f"(c[2]), "+f"(c[3])
        : "r"(a[0]), "r"(a[1]), "r"(a[2]), "r"(a[3]), "r"(b[0]), "r"(b[1]));
}

// group-local barrier: 16 CTAs per (row-tile, dir) group
__device__ __forceinline__ void groupbar(int gid, unsigned phase) {
    __syncthreads();
    if (threadIdx.x == 0) {
        __threadfence();
        atomicAdd(&g_garr[gid * 32], 1u);
        const unsigned target = phase * 16u;
        unsigned r;
        do {
            asm volatile("ld.global.acquire.gpu.u32 %0, [%1];"
                         : "=r"(r) : "l"(&g_garr[gid * 32]));
            if (r >= target) break;
            __nanosleep(32);
        } while (true);
    }
    __syncthreads();
}

// dummy launch to shift the harness's fixed ncu window (-s 5) onto xproj
__global__ void dummy_k() {}

// ---------------------------------------------------------------------------
// Prep 1: round x to fp16
// ---------------------------------------------------------------------------
__global__ __launch_bounds__(256, 4)
void round_xh(const float* __restrict__ x)
{
    const size_t i = ((size_t)blockIdx.x * 256 + threadIdx.x) * 4;
    const float4 v = *(const float4*)(x + i);
    __half2 lo = __floats2half2_rn(v.x, v.y);
    __half2 hi = __floats2half2_rn(v.z, v.w);
    *(__half2*)(g_xh + i)     = lo;
    *(__half2*)(g_xh + i + 2) = hi;
}

// ---------------------------------------------------------------------------
// Prep 2: fragment-packed fp16 Wx for m16n8k16 col-major B.
// chunk cid = ((p*2048+n)*16+kb)*4 + r4, 8 halves (16B):
//   j=0..7: ks16=j>>2, reg=(j>>1)&1, h=j&1
//   k = kb*32 + ks16*16 + reg*8 + r4*2 + h
// ---------------------------------------------------------------------------
__global__ __launch_bounds__(256, 4)
void prep_wfragh(const float* __restrict__ Wx)
{
    const uint32_t cid = blockIdx.x * 256 + threadIdx.x;   // 524288 total
    const int r4 = cid & 3;
    const int kb = (cid >> 2) & 15;
    const int n  = (cid >> 6) & 2047;
    const int p  = cid >> 17;
    const float* W = Wx + (size_t)p * H_ * G_;
    __half* o = g_Wfragh + (size_t)cid * 8;
    #pragma unroll
    for (int j = 0; j < 8; j++) {
        const int ks = j >> 2, reg = (j >> 1) & 1, h = j & 1;
        const int k = kb * 32 + ks * 16 + reg * 8 + r4 * 2 + h;
        o[j] = __float2half_rn(W[(size_t)k * G_ + n]);
    }
}

// ---------------------------------------------------------------------------
// fp16 mma.sync xproj: D[128 x 128]/CTA f32, K=512 in 16 k-blocks of 32.
// 256 thr = 8 warps (2m x 4n), warp tile 64x32, m16n8k16.
// A fp16 via 3-stage cp.async smem pipeline; B one 16B LDG per nt per kb.
// ---------------------------------------------------------------------------
#define XP_SMEM (3 * 128 * PADH * 2)

__global__ __launch_bounds__(256, 2)
void xproj_mma(const float* __restrict__ bias, int layer)
{
    extern __shared__ __half sAh[];   // [3][128][PADH]

    const int tid = threadIdx.x;
    const int lane = tid & 31, wid = tid >> 5;
    const int wm = wid & 1, wn = wid >> 1;
    const int tg = lane >> 2, r4 = lane & 3;
    const int t = blockIdx.x, d = blockIdx.z;
    const int n0 = blockIdx.y * 128;
    const int l2d = layer * 2 + d;

    const __half* Ab; size_t strA;
    if (layer == 0) {
        const int ts = d ? (T_ - 1 - t) : t;
        Ab = g_xh + (size_t)ts * H_;
        strA = (size_t)T_ * H_;        // row index = batch b
    } else {
        Ab = g_hseqh + ((size_t)d * T_ + t) * B_ * H_;
        strA = H_;
    }

    // B fragment base (halves): (p*2048+n)*512 + kb*32 + r4*8
    const __half* pB[4];
    #pragma unroll
    for (int nt = 0; nt < 4; nt++) {
        const int n = n0 + wn * 32 + nt * 8 + tg;
        pB[nt] = g_Wfragh + ((size_t)(l2d * 2048 + n)) * 512 + r4 * 8;
    }

    // A tile: 128 rows x 32 halves = 512 16B-chunks; 2 per thread
    #define ISSUE(st, kb) do {                                                 \
        _Pragma("unroll")                                                      \
        for (int i = 0; i < 2; i++) {                                          \
            const int idx = i * 256 + tid;                                     \
            const int row = idx >> 2, c8 = idx & 3;                            \
            cp16(&sAh[(st) * (128 * PADH) + row * PADH + c8 * 8],              \
                 Ab + (size_t)row * strA + (kb) * 32 + c8 * 8);                \
        }                                                                      \
        CP_COMMIT();                                                           \
    } while (0)

    float acc[4][4][4];
    #pragma unroll
    for (int mt = 0; mt < 4; mt++)
        #pragma unroll
        for (int nt = 0; nt < 4; nt++)
            #pragma unroll
            for (int i = 0; i < 4; i++) acc[mt][nt][i] = 0.f;

    ISSUE(0, 0);
    ISSUE(1, 1);

    for (int kb = 0; kb < 16; kb++) {
        uint4 bt[4];
        #pragma unroll
        for (int nt = 0; nt < 4; nt++)
            bt[nt] = *(const uint4*)(pB[nt] + kb * 32);

        if (kb == 15) { CP_WAITALL(); } else { CP_WAIT1(); }
        __syncthreads();
        if (kb + 2 < 16) ISSUE((kb + 2) % 3, kb + 2);

        const __half* sAs = sAh + (kb % 3) * (128 * PADH);
        #pragma unroll
        for (int ks = 0; ks < 2; ks++) {          // two k16 steps per k-block
            const int kk = ks * 16 + r4 * 2;
            uint32_t a[4][4];
            #pragma unroll
            for (int mt = 0; mt < 4; mt++) {
                const int m = wm * 64 + mt * 16 + tg;
                a[mt][0] = *(const uint32_t*)&sAs[m * PADH + kk];
                a[mt][1] = *(const uint32_t*)&sAs[(m + 8) * PADH + kk];
                a[mt][2] = *(const uint32_t*)&sAs[m * PADH + kk + 8];
                a[mt][3] = *(const uint32_t*)&sAs[(m + 8) * PADH + kk + 8];
            }
            #pragma unroll
            for (int mt = 0; mt < 4; mt++)
                #pragma unroll
                for (int nt = 0; nt < 4; nt++) {
                    uint32_t b2[2];
                    b2[0] = ks ? bt[nt].z : bt[nt].x;
                    b2[1] = ks ? bt[nt].w : bt[nt].y;
                    mma16(acc[mt][nt], a[mt], b2);
                }
        }
    }
    #undef ISSUE

    float* ob = g_xproj + ((size_t)d * T_ + t) * B_ * G_;
    const float* bp = bias + (size_t)l2d * G_;
    #pragma unroll
    for (int nt = 0; nt < 4; nt++) {
        const int n = n0 + wn * 32 + nt * 8 + 2 * r4;
        const float2 bv = *(const float2*)(bp + n);
        #pragma unroll
        for (int mt = 0; mt < 4; mt++) {
            const int m = wm * 64 + mt * 16 + tg;
            float2 lo = make_float2(acc[mt][nt][0] + bv.x, acc[mt][nt][1] + bv.y);
            float2 hi = make_float2(acc[mt][nt][2] + bv.x, acc[mt][nt][3] + bv.y);
            *(float2*)(ob + (size_t)m * G_ + n)       = lo;
            *(float2*)(ob + (size_t)(m + 8) * G_ + n) = hi;
        }
    }
}

// ---------------------------------------------------------------------------
// Persistent recurrence — R8/R9/R11 proven config; ONLY change: layer-0
// hseq written as fp16 (feeds the fp16 xproj of layer 1).
// ---------------------------------------------------------------------------
__global__ __launch_bounds__(128, 1)
void lstm_persist(const float* __restrict__ Wh, float* __restrict__ out, int layer)
{
    __shared__ float sW[4][16][128];
    __shared__ float sA[4][16][32];

    const int tid = threadIdx.x;
    const int tx = tid & 15;
    const int ty = tid >> 4;
    const int bidx = blockIdx.x;
    const int d   = bidx >> 6;
    const int rt  = (bidx >> 4) & 3;
    const int hcT = bidx & 15;
    const int gid = bidx >> 4;
    const int b0  = rt * 32;
    const int hc0 = hcT * 32;
    const int hc  = hc0 + tx * 2;
    const int r0  = b0 + ty * 4;

    const float* Wb = Wh + (size_t)(layer * 2 + d) * H_ * G_;

    int wk[4], wc[4];
    const float* wsrc[4];
    #pragma unroll
    for (int j = 0; j < 4; j++) {
        const int idx = j * 128 + tid;
        const int k = idx >> 5, c16 = idx & 31;
        const int gate = c16 >> 3, part = c16 & 7;
        wk[j] = k; wc[j] = c16 * 4;
        wsrc[j] = Wb + (size_t)k * G_ + gate * H_ + hc0 + part * 4;
    }
    const int ak = tid >> 3, ac = (tid & 7) * 4;

    float2 cst[4];
    #pragma unroll
    for (int r = 0; r < 4; r++) cst[r] = make_float2(0.f, 0.f);

    for (int t = 0; t < T_; t++) {
        const int p = t & 1;
        const float* xb = g_xproj + ((size_t)d * T_ + t) * B_ * G_;
        float2 xp[4][4];
        #pragma unroll
        for (int r = 0; r < 4; r++)
            #pragma unroll
            for (int g = 0; g < 4; g++)
                xp[r][g] = *(const float2*)(xb + (size_t)(r0 + r) * G_ + g * H_ + hc);

        float2 acc[4][4];
        #pragma unroll
        for (int r = 0; r < 4; r++)
            #pragma unroll
            for (int g = 0; g < 4; g++) acc[r][g] = make_float2(0.f, 0.f);

        if (t > 0) {
            const float* hsrc = &g_hT[p ^ 1][d][0][0];
            #define ISSUE2(st, kb) do {                                          \
                _Pragma("unroll")                                                \
                for (int j = 0; j < 4; j++)                                      \
                    cp16(&sW[st][wk[j]][wc[j]], wsrc[j] + (size_t)(kb) * G_);    \
                cp16(&sA[st][ak][ac], hsrc + (size_t)((kb) + ak) * B_ + b0 + ac);\
                CP_COMMIT();                                                     \
            } while (0)

            ISSUE2(0, 0); ISSUE2(1, 16); ISSUE2(2, 32);

            for (int kbi = 0; kbi < 32; kbi++) {
                CP_WAIT2();
                __syncthreads();
                const int s = kbi & 3;
                #pragma unroll
                for (int k = 0; k < 16; k++) {
                    const float4 av = *(const float4*)&sA[s][k][ty * 4];
                    float2 bg[4];
                    #pragma unroll
                    for (int g = 0; g < 4; g++)
                        bg[g] = *(const float2*)&sW[s][k][g * 32 + tx * 2];
                    const float ar[4] = {av.x, av.y, av.z, av.w};
                    #pragma unroll
                    for (int r = 0; r < 4; r++) {
                        const float2 a2 = make_float2(ar[r], ar[r]);
                        #pragma unroll
                        for (int g = 0; g < 4; g++)
                            acc[r][g] = ffma2(a2, bg[g], acc[r][g]);
                    }
                }
                const int nb = kbi + 3;
                if (nb < 32) ISSUE2(nb & 3, nb * 16);
            }
            #undef ISSUE2
        }

        float2 hv[4];
        #pragma unroll
        for (int r = 0; r < 4; r++) {
            const float i0 = sig_(acc[r][0].x + xp[r][0].x);
            const float i1 = sig_(acc[r][0].y + xp[r][0].y);
            const float f0 = sig_(acc[r][1].x + xp[r][1].x);
            const float f1 = sig_(acc[r][1].y + xp[r][1].y);
            const float q0 = tanhf(acc[r][2].x + xp[r][2].x);
            const float q1 = tanhf(acc[r][2].y + xp[r][2].y);
            const float o0 = sig_(acc[r][3].x + xp[r][3].x);
            const float o1 = sig_(acc[r][3].y + xp[r][3].y);
            cst[r].x = f0 * cst[r].x + i0 * q0;
            cst[r].y = f1 * cst[r].y + i1 * q1;
            hv[r] = make_float2(o0 * tanhf(cst[r].x), o1 * tanhf(cst[r].y));
        }

        const float4 ha = make_float4(hv[0].x, hv[1].x, hv[2].x, hv[3].x);
        const float4 hb = make_float4(hv[0].y, hv[1].y, hv[2].y, hv[3].y);
        *(float4*)&g_hT[p][d][hc][r0]     = ha;
        *(float4*)&g_hT[p][d][hc + 1][r0] = hb;

        if (layer == 0) {
            __half* hs = g_hseqh + ((size_t)d * T_ + t) * B_ * H_;
            #pragma unroll
            for (int r = 0; r < 4; r++)
                *(__half2*)(hs + (size_t)(r0 + r) * H_ + hc) =
                    __floats2half2_rn(hv[r].x, hv[r].y);
        } else {
            const int tr = d ? (T_ - 1 - t) : t;
            #pragma unroll
            for (int r = 0; r < 4; r++)
                *(float2*)(out + ((size_t)(r0 + r) * T_ + tr) * (2 * H_) + d * H_ + hc) = hv[r];
        }

        if (t < T_ - 1) groupbar(gid, (unsigned)(t + 1));
    }

    __syncthreads();
    if (tid == 0) {
        __threadfence();
        const unsigned v = atomicAdd(&g_gdone[gid * 32], 1u);
        if (v == 15u) {
            atomicExch(&g_garr[gid * 32], 0u);
            atomicExch(&g_gdone[gid * 32], 0u);
        }
    }
}

extern "C" void kernel_launch(void* const* d_in, const int* in_sizes, int n_in,
                              void* d_out, int out_size)
{
    const float* x  = (const float*)d_in[0];
    const float* Wx = (const float*)d_in[1];
    const float* Wh = (const float*)d_in[2];
    const float* b  = (const float*)d_in[3];
    float* out = (float*)d_out;

    dummy_k<<<1, 32>>>();   // shifts ncu's fixed -s 5 window onto xproj(l1)
    round_xh<<<(B_ * T_ * H_ / 4 + 255) / 256, 256>>>(x);
    prep_wfragh<<<2048, 256>>>(Wx);
    for (int l = 0; l < 2; l++) {
        xproj_mma<<<dim3(T_, 16, 2), 256, XP_SMEM>>>(b, l);
        lstm_persist<<<128, 128>>>(Wh, out, l);
    }
}

// round 16
// speedup vs baseline: 4.1686x; 2.3058x over previous
#include <cuda_runtime.h>
#include <cuda_fp16.h>
#include <cstdint>

#define B_ 128
#define T_ 256
#define H_ 512
#define G_ 2048   // 4*H
#define PADH 40   // half-element row stride for A smem (conflict-free)

// ---- static scratch ----
__device__ float  g_xproj[(size_t)2 * T_ * B_ * G_];   // [dir][t][b][4H] f32
__device__ __half g_hseqh[(size_t)2 * T_ * B_ * H_];   // [dir][t][b][H] fp16
__device__ __half g_hB[(size_t)2 * 2 * B_ * H_];       // [parity][dir][b][hc] fp16
__device__ __half g_xh[(size_t)B_ * T_ * H_];          // fp16-rounded x
__device__ __half g_Wfragh[(size_t)4 * G_ * H_];       // fragment-packed fp16 Wx
__device__ __half g_Whfrag[(size_t)4 * G_ * H_];       // fragment-packed fp16 Wh
__device__ unsigned g_garr[8 * 32];
__device__ unsigned g_gdone[8 * 32];

// ---------------- helpers ----------------
__device__ __forceinline__ float sig_(float x) { return 1.0f / (1.0f + __expf(-x)); }
__device__ __forceinline__ void cp16(void* smem, const void* gmem) {
    unsigned s = (unsigned)__cvta_generic_to_shared(smem);
    asm volatile("cp.async.cg.shared.global [%0], [%1], 16;" :: "r"(s), "l"(gmem));
}
#define CP_COMMIT()  asm volatile("cp.async.commit_group;")
#define CP_WAIT1()   asm volatile("cp.async.wait_group 1;")
#define CP_WAIT2()   asm volatile("cp.async.wait_group 2;")
#define CP_WAITALL() asm volatile("cp.async.wait_group 0;")

// fp16 m16n8k16 mma, f32 accumulate
__device__ __forceinline__ void mma16(float* c, const uint32_t* a, const uint32_t* b) {
    asm volatile(
        "mma.sync.aligned.m16n8k16.row.col.f32.f16.f16.f32 "
        "{%0,%1,%2,%3}, {%4,%5,%6,%7}, {%8,%9}, {%0,%1,%2,%3};"
        : "+f"(c[0]), "+f"(c[1]), "+f"(c[2]), "+f"(c[3])
        : "r"(a[0]), "r"(a[1]), "r"(a[2]), "r"(a[3]), "r"(b[0]), "r"(b[1]));
}

// group-local barrier: 16 CTAs per (row-tile, dir) group
__device__ __forceinline__ void groupbar(int gid, unsigned phase) {
    __syncthreads();
    if (threadIdx.x == 0) {
        __threadfence();
        atomicAdd(&g_garr[gid * 32], 1u);
        const unsigned target = phase * 16u;
        unsigned r;
        do {
            asm volatile("ld.global.acquire.gpu.u32 %0, [%1];"
                         : "=r"(r) : "l"(&g_garr[gid * 32]));
            if (r >= target) break;
            __nanosleep(32);
        } while (true);
    }
    __syncthreads();
}

__global__ void dummy_k() {}

// ---------------------------------------------------------------------------
// Prep 1: round x to fp16
// ---------------------------------------------------------------------------
__global__ __launch_bounds__(256, 4)
void round_xh(const float* __restrict__ x)
{
    const size_t i = ((size_t)blockIdx.x * 256 + threadIdx.x) * 4;
    const float4 v = *(const float4*)(x + i);
    *(__half2*)(g_xh + i)     = __floats2half2_rn(v.x, v.y);
    *(__half2*)(g_xh + i + 2) = __floats2half2_rn(v.z, v.w);
}

// ---------------------------------------------------------------------------
// Prep 2: fragment-packed fp16 weights. FIX vs R14/R15: dst selected in
// DEVICE code (host code cannot take the address of a __device__ symbol —
// that was the bug that zeroed both fragment buffers).
// ---------------------------------------------------------------------------
__global__ __launch_bounds__(256, 4)
void prep_wfrag16(const float* __restrict__ W4, int which)
{
    __half* __restrict__ dst = which ? g_Whfrag : g_Wfragh;
    const uint32_t cid = blockIdx.x * 256 + threadIdx.x;   // 524288 total
    const int r4 = cid & 3;
    const int kb = (cid >> 2) & 15;
    const int n  = (cid >> 6) & 2047;
    const int p  = cid >> 17;
    const float* W = W4 + (size_t)p * H_ * G_;
    __half* o = dst + (size_t)cid * 8;
    #pragma unroll
    for (int j = 0; j < 8; j++) {
        const int ks = j >> 2, reg = (j >> 1) & 1, h = j & 1;
        const int k = kb * 32 + ks * 16 + reg * 8 + r4 * 2 + h;
        o[j] = __float2half_rn(W[(size_t)k * G_ + n]);
    }
}

// ---------------------------------------------------------------------------
// fp16 mma.sync xproj — R13-proven body
// ---------------------------------------------------------------------------
#define XP_SMEM (3 * 128 * PADH * 2)

__global__ __launch_bounds__(256, 2)
void xproj_mma(const float* __restrict__ bias, int layer)
{
    extern __shared__ __half sAh[];   // [3][128][PADH]

    const int tid = threadIdx.x;
    const int lane = tid & 31, wid = tid >> 5;
    const int wm = wid & 1, wn = wid >> 1;
    const int tg = lane >> 2, r4 = lane & 3;
    const int t = blockIdx.x, d = blockIdx.z;
    const int n0 = blockIdx.y * 128;
    const int l2d = layer * 2 + d;

    const __half* Ab; size_t strA;
    if (layer == 0) {
        const int ts = d ? (T_ - 1 - t) : t;
        Ab = g_xh + (size_t)ts * H_;
        strA = (size_t)T_ * H_;
    } else {
        Ab = g_hseqh + ((size_t)d * T_ + t) * B_ * H_;
        strA = H_;
    }

    const __half* pB[4];
    #pragma unroll
    for (int nt = 0; nt < 4; nt++) {
        const int n = n0 + wn * 32 + nt * 8 + tg;
        pB[nt] = g_Wfragh + ((size_t)(l2d * 2048 + n)) * 512 + r4 * 8;
    }

    #define ISSUE(st, kb) do {                                                 \
        _Pragma("unroll")                                                      \
        for (int i = 0; i < 2; i++) {                                          \
            const int idx = i * 256 + tid;                                     \
            const int row = idx >> 2, c8 = idx & 3;                            \
            cp16(&sAh[(st) * (128 * PADH) + row * PADH + c8 * 8],              \
                 Ab + (size_t)row * strA + (kb) * 32 + c8 * 8);                \
        }                                                                      \
        CP_COMMIT();                                                           \
    } while (0)

    float acc[4][4][4];
    #pragma unroll
    for (int mt = 0; mt < 4; mt++)
        #pragma unroll
        for (int nt = 0; nt < 4; nt++)
            #pragma unroll
            for (int i = 0; i < 4; i++) acc[mt][nt][i] = 0.f;

    ISSUE(0, 0);
    ISSUE(1, 1);

    for (int kb = 0; kb < 16; kb++) {
        uint4 bt[4];
        #pragma unroll
        for (int nt = 0; nt < 4; nt++)
            bt[nt] = *(const uint4*)(pB[nt] + kb * 32);

        if (kb == 15) { CP_WAITALL(); } else { CP_WAIT1(); }
        __syncthreads();
        if (kb + 2 < 16) ISSUE((kb + 2) % 3, kb + 2);

        const __half* sAs = sAh + (kb % 3) * (128 * PADH);
        #pragma unroll
        for (int ks = 0; ks < 2; ks++) {
            const int kk = ks * 16 + r4 * 2;
            uint32_t a[4][4];
            #pragma unroll
            for (int mt = 0; mt < 4; mt++) {
                const int m = wm * 64 + mt * 16 + tg;
                a[mt][0] = *(const uint32_t*)&sAs[m * PADH + kk];
                a[mt][1] = *(const uint32_t*)&sAs[(m + 8) * PADH + kk];
                a[mt][2] = *(const uint32_t*)&sAs[m * PADH + kk + 8];
                a[mt][3] = *(const uint32_t*)&sAs[(m + 8) * PADH + kk + 8];
            }
            #pragma unroll
            for (int mt = 0; mt < 4; mt++)
                #pragma unroll
                for (int nt = 0; nt < 4; nt++) {
                    uint32_t b2[2];
                    b2[0] = ks ? bt[nt].z : bt[nt].x;
                    b2[1] = ks ? bt[nt].w : bt[nt].y;
                    mma16(acc[mt][nt], a[mt], b2);
                }
        }
    }
    #undef ISSUE

    float* ob = g_xproj + ((size_t)d * T_ + t) * B_ * G_;
    const float* bp = bias + (size_t)l2d * G_;
    #pragma unroll
    for (int nt = 0; nt < 4; nt++) {
        const int n = n0 + wn * 32 + nt * 8 + 2 * r4;
        const float2 bv = *(const float2*)(bp + n);
        #pragma unroll
        for (int mt = 0; mt < 4; mt++) {
            const int m = wm * 64 + mt * 16 + tg;
            float2 lo = make_float2(acc[mt][nt][0] + bv.x, acc[mt][nt][1] + bv.y);
            float2 hi = make_float2(acc[mt][nt][2] + bv.x, acc[mt][nt][3] + bv.y);
            *(float2*)(ob + (size_t)m * G_ + n)       = lo;
            *(float2*)(ob + (size_t)(m + 8) * G_ + n) = hi;
        }
    }
}

// ---------------------------------------------------------------------------
// Persistent recurrence, fp16 mma.sync step GEMM (R15 body, unchanged).
// ---------------------------------------------------------------------------
__global__ __launch_bounds__(128, 1)
void lstm_persist(float* __restrict__ out, int layer)
{
    __shared__ __half sH[4][32][PADH];   // 10.2 KB

    const int tid = threadIdx.x;
    const int lane = tid & 31, w = tid >> 5;
    const int tg = lane >> 2, r4 = lane & 3;
    const int bidx = blockIdx.x;
    const int d   = bidx >> 6;
    const int rt  = (bidx >> 4) & 3;
    const int hcT = bidx & 15;
    const int gid = bidx >> 4;
    const int b0  = rt * 32;
    const int hc0 = hcT * 32;
    const int hcp = hc0 + w * 8 + 2 * r4;
    const int l2d = layer * 2 + d;

    // Wh fragment pointers: one n8 tile per gate
    const __half* pB[4];
    #pragma unroll
    for (int g = 0; g < 4; g++) {
        const int n = g * 512 + hc0 + w * 8 + tg;
        pB[g] = g_Whfrag + ((size_t)(l2d * 2048 + n)) * 512 + r4 * 8;
    }

    // A cp.async coords: 32 rows x 32 halves = 128 16B-chunks, 1 per thread
    const int arow = tid >> 2, ac8 = (tid & 3) * 8;

    float2 cst[4];
    #pragma unroll
    for (int r = 0; r < 4; r++) cst[r] = make_float2(0.f, 0.f);

    for (int t = 0; t < T_; t++) {
        const int p = t & 1;

        // prefetch xproj slice (hidden under GEMM)
        const float* xb = g_xproj + ((size_t)d * T_ + t) * B_ * G_;
        float2 xp[4][4];
        #pragma unroll
        for (int r = 0; r < 4; r++) {
            const int br = b0 + tg + r * 8;
            #pragma unroll
            for (int g = 0; g < 4; g++)
                xp[r][g] = *(const float2*)(xb + (size_t)br * G_ + g * H_ + hcp);
        }

        float acc[2][4][4];
        #pragma unroll
        for (int mt = 0; mt < 2; mt++)
            #pragma unroll
            for (int g = 0; g < 4; g++)
                #pragma unroll
                for (int i = 0; i < 4; i++) acc[mt][g][i] = 0.f;

        if (t > 0) {
            const __half* hsrc = g_hB + (size_t)((p ^ 1) * 2 + d) * B_ * H_;

            #define HISSUE(st, kb) do {                                          \
                cp16(&sH[st][arow][ac8],                                         \
                     hsrc + (size_t)(b0 + arow) * H_ + (kb) * 32 + ac8);         \
                CP_COMMIT();                                                     \
            } while (0)

            #define HPFETCH(BT, kb) do {                                         \
                _Pragma("unroll")                                                \
                for (int g = 0; g < 4; g++)                                      \
                    BT[g] = *(const uint4*)(pB[g] + (kb) * 32);                  \
            } while (0)

            #define HKSTEP(kb, BT) do {                                          \
                if ((kb) == 15)      { CP_WAITALL(); }                           \
                else if ((kb) == 14) { CP_WAIT1(); }                             \
                else                 { CP_WAIT2(); }                             \
                __syncthreads();                                                 \
                if ((kb) + 3 < 16) HISSUE(((kb) + 3) & 3, (kb) + 3);             \
                const __half* sAs = &sH[(kb) & 3][0][0];                         \
                _Pragma("unroll")                                                \
                for (int ks = 0; ks < 2; ks++) {                                 \
                    const int kk = ks * 16 + r4 * 2;                             \
                    uint32_t a[2][4];                                            \
                    _Pragma("unroll")                                            \
                    for (int mt = 0; mt < 2; mt++) {                             \
                        const int m = mt * 16 + tg;                              \
                        a[mt][0] = *(const uint32_t*)&sAs[m * PADH + kk];        \
                        a[mt][1] = *(const uint32_t*)&sAs[(m + 8) * PADH + kk];  \
                        a[mt][2] = *(const uint32_t*)&sAs[m * PADH + kk + 8];    \
                        a[mt][3] = *(const uint32_t*)&sAs[(m + 8) * PADH + kk + 8];\
                    }                                                            \
                    _Pragma("unroll")                                            \
                    for (int mt = 0; mt < 2; mt++)                               \
                        _Pragma("unroll")                                        \
                        for (int g = 0; g < 4; g++) {                            \
                            uint32_t b2[2];                                      \
                            b2[0] = ks ? BT[g].z : BT[g].x;                      \
                            b2[1] = ks ? BT[g].w : BT[g].y;                      \
                            mma16(acc[mt][g], a[mt], b2);                        \
                        }                                                        \
                }                                                                \
            } while (0)

            uint4 bt0[4], bt1[4];
            HISSUE(0, 0); HISSUE(1, 1); HISSUE(2, 2);
            HPFETCH(bt0, 0);

            #pragma unroll
            for (int kb2 = 0; kb2 < 16; kb2 += 2) {
                HPFETCH(bt1, kb2 + 1);
                HKSTEP(kb2, bt0);
                if (kb2 + 2 < 16) HPFETCH(bt0, kb2 + 2);
                HKSTEP(kb2 + 1, bt1);
            }
            #undef HISSUE
            #undef HPFETCH
            #undef HKSTEP
        }

        // epilogue: gates -> cell -> h
        float2 hv[4];
        #pragma unroll
        for (int r = 0; r < 4; r++) {
            const int mt = r >> 1, pr = (r & 1) * 2;
            const float i0 = sig_(acc[mt][0][pr]     + xp[r][0].x);
            const float i1 = sig_(acc[mt][0][pr + 1] + xp[r][0].y);
            const float f0 = sig_(acc[mt][1][pr]     + xp[r][1].x);
            const float f1 = sig_(acc[mt][1][pr + 1] + xp[r][1].y);
            const float q0 = tanhf(acc[mt][2][pr]     + xp[r][2].x);
            const float q1 = tanhf(acc[mt][2][pr + 1] + xp[r][2].y);
            const float o0 = sig_(acc[mt][3][pr]     + xp[r][3].x);
            const float o1 = sig_(acc[mt][3][pr + 1] + xp[r][3].y);
            cst[r].x = f0 * cst[r].x + i0 * q0;
            cst[r].y = f1 * cst[r].y + i1 * q1;
            hv[r] = make_float2(o0 * tanhf(cst[r].x), o1 * tanhf(cst[r].y));
        }

        // store h fp16 for next step's GEMM
        __half* hw = g_hB + (size_t)(p * 2 + d) * B_ * H_;
        #pragma unroll
        for (int r = 0; r < 4; r++) {
            const int br = b0 + tg + r * 8;
            *(__half2*)(hw + (size_t)br * H_ + hcp) =
                __floats2half2_rn(hv[r].x, hv[r].y);
        }

        if (layer == 0) {
            __half* hs = g_hseqh + ((size_t)d * T_ + t) * B_ * H_;
            #pragma unroll
            for (int r = 0; r < 4; r++) {
                const int br = b0 + tg + r * 8;
                *(__half2*)(hs + (size_t)br * H_ + hcp) =
                    __floats2half2_rn(hv[r].x, hv[r].y);
            }
        } else {
            const int tr = d ? (T_ - 1 - t) : t;
            #pragma unroll
            for (int r = 0; r < 4; r++) {
                const int br = b0 + tg + r * 8;
                *(float2*)(out + ((size_t)br * T_ + tr) * (2 * H_) + d * H_ + hcp) = hv[r];
            }
        }

        if (t < T_ - 1) groupbar(gid, (unsigned)(t + 1));
    }

    // per-group reset for next launch / graph replay
    __syncthreads();
    if (tid == 0) {
        __threadfence();
        const unsigned v = atomicAdd(&g_gdone[gid * 32], 1u);
        if (v == 15u) {
            atomicExch(&g_garr[gid * 32], 0u);
            atomicExch(&g_gdone[gid * 32], 0u);
        }
    }
}

extern "C" void kernel_launch(void* const* d_in, const int* in_sizes, int n_in,
                              void* d_out, int out_size)
{
    const float* x  = (const float*)d_in[0];
    const float* Wx = (const float*)d_in[1];
    const float* Wh = (const float*)d_in[2];
    const float* b  = (const float*)d_in[3];
    float* out = (float*)d_out;

    static bool attr_done = false;
    if (!attr_done) {
        cudaFuncSetAttribute(xproj_mma, cudaFuncAttributeMaxDynamicSharedMemorySize, XP_SMEM);
        attr_done = true;
    }

    dummy_k<<<1, 32>>>();
    round_xh<<<(B_ * T_ * H_ / 4 + 255) / 256, 256>>>(x);
    prep_wfrag16<<<2048, 256>>>(Wx, 0);   // -> g_Wfragh (device-side select)
    prep_wfrag16<<<2048, 256>>>(Wh, 1);   // -> g_Whfrag
    for (int l = 0; l < 2; l++) {
        xproj_mma<<<dim3(T_, 16, 2), 256, XP_SMEM>>>(b, l);
        lstm_persist<<<128, 128>>>(out, l);
    }
}